// round 14
// baseline (speedup 1.0000x reference)
#include <cuda_runtime.h>
#include <cstdint>

#define FULLMASK 0xffffffffu
typedef unsigned long long u64;

// ---- f32x2 packed helpers (sm_103a) ----
__device__ __forceinline__ u64 pk2(float lo, float hi) {
    u64 r; asm("mov.b64 %0,{%1,%2};" : "=l"(r) : "f"(lo), "f"(hi)); return r;
}
__device__ __forceinline__ void up2(u64 v, float& lo, float& hi) {
    asm("mov.b64 {%0,%1},%2;" : "=f"(lo), "=f"(hi) : "l"(v));
}
__device__ __forceinline__ u64 fma2(u64 a, u64 b, u64 c) {
    u64 d; asm("fma.rn.f32x2 %0,%1,%2,%3;" : "=l"(d) : "l"(a), "l"(b), "l"(c)); return d;
}
__device__ __forceinline__ u64 mul2(u64 a, u64 b) {
    u64 d; asm("mul.rn.f32x2 %0,%1,%2;" : "=l"(d) : "l"(a), "l"(b)); return d;
}

// ============ Fused kernel: LN+linear (angles) -> smem handoff -> circuit ============
// Block = 256 threads = 8 warps = 64 rows.
// Phase 1: per warp, 2 groups of 4 rows; DOT accumulators packed f32x2 (dots are
//          2 fma2/q/row/j instead of 4 fma); sum/sumsq scalar; e double-buffered.
// Phase 2: R11 circuit: 4 lanes/row, 32 x f32x2/thread (pair = q5), tan-form gates,
//          global cos factors folded into g table as F^2. (verified, unchanged)
__global__ __launch_bounds__(256, 2) void qsco_fused(const float* __restrict__ E,
                                                     const float* __restrict__ W_pre,
                                                     const float* __restrict__ ln_gamma,
                                                     const float* __restrict__ ln_beta,
                                                     const float* __restrict__ b_pre,
                                                     const float* __restrict__ theta,
                                                     const float* __restrict__ W_post,
                                                     const float* __restrict__ b_post,
                                                     float* __restrict__ out,
                                                     int B) {
    __shared__ float4 sWg4[8 * 128];            // 16 KB: gamma ⊙ W_pre
    __shared__ float sGw[32], sBw[32];
    __shared__ float sSg[8], sCq[8];
    __shared__ __align__(16) float2 scs[64 * 10];  // (c,s) per row, stride 10 -> no bank conflicts
    __shared__ __align__(16) float2 sG2[4 * 34];
    __shared__ float sct[8], sst[8], sbp;

    int tid = threadIdx.x;
    int lane = tid & 31;
    int wrp = tid >> 5;

    // ---- block-constant prep (weights + Sg/Cq + trig + g table) ----
    {
        const float4* Wp4 = (const float4*)W_pre;
        const float4* g4  = (const float4*)ln_gamma;
        const float4* b4  = (const float4*)ln_beta;
        float gw[4], bw[4];
        #pragma unroll
        for (int j = 0; j < 4; j++) {
            int i = tid + 256 * j;
            float4 w = Wp4[i];
            float4 g = g4[i & 127];
            float4 b = b4[i & 127];
            float gsum = 0.f, bsum = 0.f;
            gsum = fmaf(g.x, w.x, gsum); gsum = fmaf(g.y, w.y, gsum);
            gsum = fmaf(g.z, w.z, gsum); gsum = fmaf(g.w, w.w, gsum);
            bsum = fmaf(b.x, w.x, bsum); bsum = fmaf(b.y, w.y, bsum);
            bsum = fmaf(b.z, w.z, bsum); bsum = fmaf(b.w, w.w, bsum);
            gw[j] = gsum; bw[j] = bsum;
            w.x *= g.x; w.y *= g.y; w.z *= g.z; w.w *= g.w;
            sWg4[i] = w;
        }
        #pragma unroll
        for (int m = 16; m; m >>= 1) {
            #pragma unroll
            for (int j = 0; j < 4; j++) {
                gw[j] += __shfl_xor_sync(FULLMASK, gw[j], m);
                bw[j] += __shfl_xor_sync(FULLMASK, bw[j], m);
            }
        }
        if (lane == 0) {
            #pragma unroll
            for (int j = 0; j < 4; j++) {
                sGw[wrp * 4 + j] = gw[j];
                sBw[wrp * 4 + j] = bw[j];
            }
        }
        if (tid < 8) {
            float h = 0.5f * theta[tid];
            sct[tid] = cosf(h);
            sst[tid] = sinf(h);
        }
        if (tid >= 128 && tid < 256) {
            int t = tid - 128;
            float fa = 1.f;
            #pragma unroll
            for (int i = 0; i < 8; i++) {
                float cc = cosf(0.5f * theta[i]);
                fa *= cc * cc;
            }
            float scale = fa * fa;
            int lsub = t >> 5, r = t & 31;
            int bb0 = r | (lsub << 6);
            int bb1 = bb0 | 32;
            float g0 = 0.f, g1 = 0.f;
            #pragma unroll
            for (int i = 0; i < 8; i++) {
                float w = W_post[i];
                g0 += w * (((bb0 >> i) & 1) ? -1.f : 1.f);
                g1 += w * (((bb1 >> i) & 1) ? -1.f : 1.f);
            }
            sG2[lsub * 34 + r] = make_float2(g0 * scale, g1 * scale);
        }
        if (tid == 16) sbp = b_post[0];
    }
    __syncthreads();
    if (tid < 8) {
        int h = tid & 1, jj = tid >> 1;
        float s = 0.f, cc = 0.f;
        #pragma unroll
        for (int m = 0; m < 4; m++) {
            s  += sGw[(4 * h + m) * 4 + jj];
            cc += sBw[(4 * h + m) * 4 + jj];
        }
        sSg[tid] = s;
        sCq[tid] = cc + b_pre[tid];
    }
    __syncthreads();

    int blkrow0 = blockIdx.x * 64;

    // ---- Phase 1: angles for 8 rows per warp (2 groups of 4), dots packed ----
    #pragma unroll
    for (int g = 0; g < 2; g++) {
        int row0 = blkrow0 + wrp * 8 + g * 4;

        float s_[4], ss_[4];
        u64 D2[4][8];
        #pragma unroll
        for (int rr = 0; rr < 4; rr++) {
            s_[rr] = 0.f; ss_[rr] = 0.f;
            #pragma unroll
            for (int q = 0; q < 8; q++) D2[rr][q] = 0;
        }

        const float4* er[4];
        #pragma unroll
        for (int rr = 0; rr < 4; rr++) {
            int r = row0 + rr;
            if (r >= B) r = B - 1;
            er[rr] = (const float4*)(E + (size_t)r * 512);
        }

        // double-buffered e loads across j
        float4 ef[4];
        #pragma unroll
        for (int rr = 0; rr < 4; rr++) ef[rr] = __ldcs(&er[rr][lane]);

        #pragma unroll
        for (int j = 0; j < 4; j++) {
            float4 en[4];
            if (j < 3) {
                #pragma unroll
                for (int rr = 0; rr < 4; rr++) en[rr] = __ldcs(&er[rr][(j + 1) * 32 + lane]);
            }
            u64 elo[4], ehi[4];
            #pragma unroll
            for (int rr = 0; rr < 4; rr++) {
                elo[rr] = pk2(ef[rr].x, ef[rr].y);
                ehi[rr] = pk2(ef[rr].z, ef[rr].w);
            }
            #pragma unroll
            for (int rr = 0; rr < 4; rr++) {
                s_[rr] += (ef[rr].x + ef[rr].y) + (ef[rr].z + ef[rr].w);
                float ssv = ss_[rr];
                ssv = fmaf(ef[rr].x, ef[rr].x, ssv);
                ssv = fmaf(ef[rr].y, ef[rr].y, ssv);
                ssv = fmaf(ef[rr].z, ef[rr].z, ssv);
                ssv = fmaf(ef[rr].w, ef[rr].w, ssv);
                ss_[rr] = ssv;
            }
            #pragma unroll
            for (int q = 0; q < 8; q++) {
                float4 wf = sWg4[q * 128 + j * 32 + lane];
                u64 wlo = pk2(wf.x, wf.y);
                u64 whi = pk2(wf.z, wf.w);
                #pragma unroll
                for (int rr = 0; rr < 4; rr++) {
                    D2[rr][q] = fma2(elo[rr], wlo, D2[rr][q]);
                    D2[rr][q] = fma2(ehi[rr], whi, D2[rr][q]);
                }
            }
            if (j < 3) {
                #pragma unroll
                for (int rr = 0; rr < 4; rr++) ef[rr] = en[rr];
            }
        }

        // collapse packed dots, then routed reduction (verified datapath)
        float V[4][10];
        #pragma unroll
        for (int rr = 0; rr < 4; rr++) {
            V[rr][0] = s_[rr];
            V[rr][1] = ss_[rr];
            #pragma unroll
            for (int q = 0; q < 8; q++) {
                float lo, hi;
                up2(D2[rr][q], lo, hi);
                V[rr][2 + q] = lo + hi;
            }
        }

        #pragma unroll
        for (int rr = 0; rr < 4; rr++)
            #pragma unroll
            for (int k = 0; k < 10; k++)
                V[rr][k] += __shfl_xor_sync(FULLMASK, V[rr][k], 16);
        bool up = (lane & 16) != 0;
        #pragma unroll
        for (int k = 0; k < 10; k++) {
            V[0][k] = up ? V[2][k] : V[0][k];
            V[1][k] = up ? V[3][k] : V[1][k];
        }
        #pragma unroll
        for (int k = 0; k < 10; k++) {
            V[0][k] += __shfl_xor_sync(FULLMASK, V[0][k], 8);
            V[1][k] += __shfl_xor_sync(FULLMASK, V[1][k], 8);
        }
        bool sel1 = (lane & 8) != 0;
        float A[10];
        #pragma unroll
        for (int k = 0; k < 10; k++) {
            float v = sel1 ? V[1][k] : V[0][k];
            v += __shfl_xor_sync(FULLMASK, v, 4);
            v += __shfl_xor_sync(FULLMASK, v, 2);
            v += __shfl_xor_sync(FULLMASK, v, 1);
            A[k] = v;
        }

        const float inv512 = 1.0f / 512.0f;
        float mu = A[0] * inv512;
        float var = fmaf(-mu, mu, A[1] * inv512);
        float inv = rsqrtf(var + 1e-5f);

        int j = lane & 7;
        float ang = fmaf(inv, fmaf(-mu, sSg[j], A[2 + j]), sCq[j]);
        float s, c;
        __sincosf(0.5f * ang, &s, &c);
        int rowInBlk = wrp * 8 + g * 4 + (lane >> 3);
        scs[rowInBlk * 10 + j] = make_float2(c, s);
    }
    __syncthreads();

    // ---- Phase 2: circuit (R11, tan-form; verified, unchanged) ----
    int warp = blockIdx.x * 8 + wrp;
    int myrow = warp * 8 + (lane >> 2);
    int rowInBlk = wrp * 8 + (lane >> 2);

    const float4* ap = (const float4*)&scs[rowInBlk * 10];
    float4 v0 = ap[0], v1 = ap[1], v2 = ap[2], v3 = ap[3];
    float ca[8], sa[8];
    ca[0] = v0.x; sa[0] = v0.y; ca[1] = v0.z; sa[1] = v0.w;
    ca[2] = v1.x; sa[2] = v1.y; ca[3] = v1.z; sa[3] = v1.w;
    ca[4] = v2.x; sa[4] = v2.y; ca[5] = v2.z; sa[5] = v2.w;
    ca[6] = v3.x; sa[6] = v3.y; ca[7] = v3.z; sa[7] = v3.w;

    int b6 = lane & 1;
    int b7 = (lane >> 1) & 1;
    bool c7 = b7 != 0;
    int lbase = lane & ~3;
    int s0 = lbase | b6 | ((b7 ^ b6) << 1);
    int s1 = s0 ^ 1;

    // Initial product state (packed over qubit5)
    u64 amp2[32];
    {
        float w67 = (b6 ? sa[6] : ca[6]) * (b7 ? sa[7] : ca[7]);
        amp2[0] = pk2(w67 * ca[5], w67 * sa[5]);
        #pragma unroll
        for (int q = 0; q < 5; q++) {
            u64 cab = pk2(ca[q], ca[q]);
            u64 sab = pk2(sa[q], sa[q]);
            const int cnt = 1 << q;
            #pragma unroll
            for (int r = 0; r < 16; r++) {
                if (r < cnt) {
                    amp2[r + cnt] = mul2(amp2[r], sab);
                    amp2[r]       = mul2(amp2[r], cab);
                }
            }
        }
    }

    // tan-form constants
    float tq[8];
    #pragma unroll
    for (int q = 0; q < 8; q++) tq[q] = sst[q] / sct[q];
    u64 nt0b = pk2(-tq[0], -tq[0]), pt0b = pk2(tq[0], tq[0]);
    u64 ntb[5], ptb[5];
    #pragma unroll
    for (int q = 1; q < 5; q++) {
        ntb[q] = pk2(-tq[q], -tq[q]);
        ptb[q] = pk2(tq[q], tq[q]);
    }
    u64 t5v = pk2(-tq[5], tq[5]);
    float sg6t = b6 ? tq[6] : -tq[6];
    float sg7t = b7 ? tq[7] : -tq[7];
    u64 sg6tb = pk2(sg6t, sg6t);
    u64 sg7tb = pk2(sg7t, sg7t);

    #pragma unroll
    for (int d = 0; d < 2; d++) {
        // CNOT(0,1)..(3,4): register renames (free)
        #pragma unroll
        for (int r = 0; r < 32; r++)
            if ((r & 1) && !(r & 2)) { u64 t = amp2[r]; amp2[r] = amp2[r | 2]; amp2[r | 2] = t; }
        #pragma unroll
        for (int r = 0; r < 32; r++)
            if ((r & 2) && !(r & 4)) { u64 t = amp2[r]; amp2[r] = amp2[r | 4]; amp2[r | 4] = t; }
        #pragma unroll
        for (int r = 0; r < 32; r++)
            if ((r & 4) && !(r & 8)) { u64 t = amp2[r]; amp2[r] = amp2[r | 8]; amp2[r | 8] = t; }
        #pragma unroll
        for (int r = 0; r < 32; r++)
            if ((r & 8) && !(r & 16)) { u64 t = amp2[r]; amp2[r] = amp2[r | 16]; amp2[r | 16] = t; }
        // CNOT(4,5) absorbed half-swap + merged CNOT(5,6)+(6,7) lane gather
        #pragma unroll
        for (int r = 0; r < 32; r++) {
            float lo, hi;
            up2(amp2[r], lo, hi);
            float x0 = (r & 16) ? hi : lo;
            float x1 = (r & 16) ? lo : hi;
            float nlo = __shfl_sync(FULLMASK, x0, s0);
            float nhi = __shfl_sync(FULLMASK, x1, s1);
            amp2[r] = pk2(nlo, nhi);
        }
        // fused CNOT(7,0)+RY(0), tan form
        #pragma unroll
        for (int r = 0; r < 32; r += 2) {
            u64 a0 = amp2[r], a1 = amp2[r + 1];
            u64 x0 = c7 ? a1 : a0;
            u64 x1 = c7 ? a0 : a1;
            amp2[r]     = fma2(nt0b, x1, x0);
            amp2[r + 1] = fma2(pt0b, x0, x1);
        }
        // RY(1..4), tan form
        #pragma unroll
        for (int q = 1; q < 5; q++) {
            const int bq = 1 << q;
            #pragma unroll
            for (int r = 0; r < 32; r++) {
                if (!(r & bq)) {
                    int r2 = r | bq;
                    u64 a0 = amp2[r], a1 = amp2[r2];
                    amp2[r]  = fma2(ntb[q], a1, a0);
                    amp2[r2] = fma2(ptb[q], a0, a1);
                }
            }
        }
        // RY(5): within-pair
        #pragma unroll
        for (int r = 0; r < 32; r++) {
            float lo, hi;
            up2(amp2[r], lo, hi);
            amp2[r] = fma2(t5v, pk2(hi, lo), amp2[r]);
        }
        // RY(6): lane xor1
        #pragma unroll
        for (int r = 0; r < 32; r++) {
            float lo, hi;
            up2(amp2[r], lo, hi);
            float plo = __shfl_xor_sync(FULLMASK, lo, 1);
            float phi = __shfl_xor_sync(FULLMASK, hi, 1);
            amp2[r] = fma2(sg6tb, pk2(plo, phi), amp2[r]);
        }
        // RY(7): lane xor2
        #pragma unroll
        for (int r = 0; r < 32; r++) {
            float lo, hi;
            up2(amp2[r], lo, hi);
            float plo = __shfl_xor_sync(FULLMASK, lo, 2);
            float phi = __shfl_xor_sync(FULLMASK, hi, 2);
            amp2[r] = fma2(sg7tb, pk2(plo, phi), amp2[r]);
        }
    }

    // Readout (g table carries F^2)
    int lsub = lane & 3;
    const u64* gp = (const u64*)(sG2 + lsub * 34);
    u64 tot2 = pk2(0.f, 0.f);
    #pragma unroll
    for (int r = 0; r < 32; r++) {
        u64 p2 = mul2(amp2[r], amp2[r]);
        tot2 = fma2(p2, gp[r], tot2);
    }
    float tlo, thi;
    up2(tot2, tlo, thi);
    float tot = tlo + thi;
    tot += __shfl_xor_sync(FULLMASK, tot, 1);
    tot += __shfl_xor_sync(FULLMASK, tot, 2);

    if (lsub == 0 && myrow < B)
        out[myrow] = tot + sbp;
}

extern "C" void kernel_launch(void* const* d_in, const int* in_sizes, int n_in,
                              void* d_out, int out_size) {
    const float* E        = (const float*)d_in[0];
    const float* ln_gamma = (const float*)d_in[1];
    const float* ln_beta  = (const float*)d_in[2];
    const float* W_pre    = (const float*)d_in[3];
    const float* b_pre    = (const float*)d_in[4];
    const float* theta    = (const float*)d_in[5];
    const float* W_post   = (const float*)d_in[6];
    const float* b_post   = (const float*)d_in[7];
    float* out = (float*)d_out;
    int B = out_size;

    qsco_fused<<<(B + 63) / 64, 256>>>(E, W_pre, ln_gamma, ln_beta, b_pre,
                                       theta, W_post, b_post, out, B);
}

// round 15
// speedup vs baseline: 1.1076x; 1.1076x over previous
#include <cuda_runtime.h>
#include <cstdint>

#define FULLMASK 0xffffffffu
typedef unsigned long long u64;

// ---- f32x2 packed helpers (sm_103a) ----
__device__ __forceinline__ u64 pk2(float lo, float hi) {
    u64 r; asm("mov.b64 %0,{%1,%2};" : "=l"(r) : "f"(lo), "f"(hi)); return r;
}
__device__ __forceinline__ void up2(u64 v, float& lo, float& hi) {
    asm("mov.b64 {%0,%1},%2;" : "=f"(lo), "=f"(hi) : "l"(v));
}
__device__ __forceinline__ u64 fma2(u64 a, u64 b, u64 c) {
    u64 d; asm("fma.rn.f32x2 %0,%1,%2,%3;" : "=l"(d) : "l"(a), "l"(b), "l"(c)); return d;
}
__device__ __forceinline__ u64 mul2(u64 a, u64 b) {
    u64 d; asm("mul.rn.f32x2 %0,%1,%2;" : "=l"(d) : "l"(a), "l"(b)); return d;
}

// ============ Fused persistent kernel: per-tile LN+linear -> smem -> circuit ============
// Block = 256 threads = 8 warps; tile = 64 rows; block loops over tiles.
// Per-block prep (weights, Sg/Cq, trig, g table) done ONCE per persistent block.
__global__ __launch_bounds__(256, 2) void qsco_fused(const float* __restrict__ E,
                                                     const float* __restrict__ W_pre,
                                                     const float* __restrict__ ln_gamma,
                                                     const float* __restrict__ ln_beta,
                                                     const float* __restrict__ b_pre,
                                                     const float* __restrict__ theta,
                                                     const float* __restrict__ W_post,
                                                     const float* __restrict__ b_post,
                                                     float* __restrict__ out,
                                                     int B, int numTiles) {
    __shared__ float4 sWg4[8 * 128];            // 16 KB: gamma ⊙ W_pre
    __shared__ float sGw[32], sBw[32];
    __shared__ float sSg[8], sCq[8];
    __shared__ __align__(16) float2 scs[64 * 10];  // (c,s) per row, stride 10 -> no bank conflicts
    __shared__ __align__(16) float2 sG2[4 * 34];
    __shared__ float sct[8], sst[8], sbp;

    int tid = threadIdx.x;
    int lane = tid & 31;
    int wrp = tid >> 5;

    // ---- once-per-block prep (weights + Sg/Cq + trig + g table) ----
    {
        const float4* Wp4 = (const float4*)W_pre;
        const float4* g4  = (const float4*)ln_gamma;
        const float4* b4  = (const float4*)ln_beta;
        float gw[4], bw[4];
        #pragma unroll
        for (int j = 0; j < 4; j++) {
            int i = tid + 256 * j;
            float4 w = Wp4[i];
            float4 g = g4[i & 127];
            float4 b = b4[i & 127];
            float gsum = 0.f, bsum = 0.f;
            gsum = fmaf(g.x, w.x, gsum); gsum = fmaf(g.y, w.y, gsum);
            gsum = fmaf(g.z, w.z, gsum); gsum = fmaf(g.w, w.w, gsum);
            bsum = fmaf(b.x, w.x, bsum); bsum = fmaf(b.y, w.y, bsum);
            bsum = fmaf(b.z, w.z, bsum); bsum = fmaf(b.w, w.w, bsum);
            gw[j] = gsum; bw[j] = bsum;
            w.x *= g.x; w.y *= g.y; w.z *= g.z; w.w *= g.w;
            sWg4[i] = w;
        }
        #pragma unroll
        for (int m = 16; m; m >>= 1) {
            #pragma unroll
            for (int j = 0; j < 4; j++) {
                gw[j] += __shfl_xor_sync(FULLMASK, gw[j], m);
                bw[j] += __shfl_xor_sync(FULLMASK, bw[j], m);
            }
        }
        if (lane == 0) {
            #pragma unroll
            for (int j = 0; j < 4; j++) {
                sGw[wrp * 4 + j] = gw[j];
                sBw[wrp * 4 + j] = bw[j];
            }
        }
        if (tid < 8) {
            float h = 0.5f * theta[tid];
            sct[tid] = cosf(h);
            sst[tid] = sinf(h);
        }
        if (tid >= 128 && tid < 256) {
            int t = tid - 128;
            float fa = 1.f;
            #pragma unroll
            for (int i = 0; i < 8; i++) {
                float cc = cosf(0.5f * theta[i]);
                fa *= cc * cc;
            }
            float scale = fa * fa;
            int lsub = t >> 5, r = t & 31;
            int bb0 = r | (lsub << 6);
            int bb1 = bb0 | 32;
            float g0 = 0.f, g1 = 0.f;
            #pragma unroll
            for (int i = 0; i < 8; i++) {
                float w = W_post[i];
                g0 += w * (((bb0 >> i) & 1) ? -1.f : 1.f);
                g1 += w * (((bb1 >> i) & 1) ? -1.f : 1.f);
            }
            sG2[lsub * 34 + r] = make_float2(g0 * scale, g1 * scale);
        }
        if (tid == 16) sbp = b_post[0];
    }
    __syncthreads();
    if (tid < 8) {
        int h = tid & 1, jj = tid >> 1;
        float s = 0.f, cc = 0.f;
        #pragma unroll
        for (int m = 0; m < 4; m++) {
            s  += sGw[(4 * h + m) * 4 + jj];
            cc += sBw[(4 * h + m) * 4 + jj];
        }
        sSg[tid] = s;
        sCq[tid] = cc + b_pre[tid];
    }
    __syncthreads();

    // ---- persistent tile loop ----
    for (int tile = blockIdx.x; tile < numTiles; tile += gridDim.x) {
        int blkrow0 = tile * 64;

        // ---- Phase 1: angles for 8 rows per warp (2 groups of 4) ----
        #pragma unroll
        for (int g = 0; g < 2; g++) {
            int row0 = blkrow0 + wrp * 8 + g * 4;

            float V[4][10];
            #pragma unroll
            for (int rr = 0; rr < 4; rr++)
                #pragma unroll
                for (int k = 0; k < 10; k++) V[rr][k] = 0.f;

            const float4* er[4];
            #pragma unroll
            for (int rr = 0; rr < 4; rr++) {
                int r = row0 + rr;
                if (r >= B) r = B - 1;
                er[rr] = (const float4*)(E + (size_t)r * 512);
            }

            #pragma unroll
            for (int j = 0; j < 4; j++) {
                float4 e[4];
                #pragma unroll
                for (int rr = 0; rr < 4; rr++) e[rr] = __ldcs(&er[rr][j * 32 + lane]);
                #pragma unroll
                for (int rr = 0; rr < 4; rr++) {
                    V[rr][0] += (e[rr].x + e[rr].y) + (e[rr].z + e[rr].w);
                    float ssv = V[rr][1];
                    ssv = fmaf(e[rr].x, e[rr].x, ssv);
                    ssv = fmaf(e[rr].y, e[rr].y, ssv);
                    ssv = fmaf(e[rr].z, e[rr].z, ssv);
                    ssv = fmaf(e[rr].w, e[rr].w, ssv);
                    V[rr][1] = ssv;
                }
                #pragma unroll
                for (int q = 0; q < 8; q++) {
                    float4 wv = sWg4[q * 128 + j * 32 + lane];
                    #pragma unroll
                    for (int rr = 0; rr < 4; rr++) {
                        float a = V[rr][2 + q];
                        a = fmaf(e[rr].x, wv.x, a);
                        a = fmaf(e[rr].y, wv.y, a);
                        a = fmaf(e[rr].z, wv.z, a);
                        a = fmaf(e[rr].w, wv.w, a);
                        V[rr][2 + q] = a;
                    }
                }
            }

            // Routed reduction: lane ends with row (lane>>3)'s 10 sums
            #pragma unroll
            for (int rr = 0; rr < 4; rr++)
                #pragma unroll
                for (int k = 0; k < 10; k++)
                    V[rr][k] += __shfl_xor_sync(FULLMASK, V[rr][k], 16);
            bool up = (lane & 16) != 0;
            #pragma unroll
            for (int k = 0; k < 10; k++) {
                V[0][k] = up ? V[2][k] : V[0][k];
                V[1][k] = up ? V[3][k] : V[1][k];
            }
            #pragma unroll
            for (int k = 0; k < 10; k++) {
                V[0][k] += __shfl_xor_sync(FULLMASK, V[0][k], 8);
                V[1][k] += __shfl_xor_sync(FULLMASK, V[1][k], 8);
            }
            bool sel1 = (lane & 8) != 0;
            float A[10];
            #pragma unroll
            for (int k = 0; k < 10; k++) {
                float v = sel1 ? V[1][k] : V[0][k];
                v += __shfl_xor_sync(FULLMASK, v, 4);
                v += __shfl_xor_sync(FULLMASK, v, 2);
                v += __shfl_xor_sync(FULLMASK, v, 1);
                A[k] = v;
            }

            const float inv512 = 1.0f / 512.0f;
            float mu = A[0] * inv512;
            float var = fmaf(-mu, mu, A[1] * inv512);
            float inv = rsqrtf(var + 1e-5f);

            int j = lane & 7;
            float ang = fmaf(inv, fmaf(-mu, sSg[j], A[2 + j]), sCq[j]);
            float s, c;
            __sincosf(0.5f * ang, &s, &c);
            int rowInBlk = wrp * 8 + g * 4 + (lane >> 3);
            scs[rowInBlk * 10 + j] = make_float2(c, s);
        }
        __syncthreads();

        // ---- Phase 2: circuit (R11 tan-form, verified) ----
        int rowInBlk = wrp * 8 + (lane >> 2);
        int myrow = blkrow0 + rowInBlk;

        const float4* ap = (const float4*)&scs[rowInBlk * 10];
        float4 v0 = ap[0], v1 = ap[1], v2 = ap[2], v3 = ap[3];
        float ca[8], sa[8];
        ca[0] = v0.x; sa[0] = v0.y; ca[1] = v0.z; sa[1] = v0.w;
        ca[2] = v1.x; sa[2] = v1.y; ca[3] = v1.z; sa[3] = v1.w;
        ca[4] = v2.x; sa[4] = v2.y; ca[5] = v2.z; sa[5] = v2.w;
        ca[6] = v3.x; sa[6] = v3.y; ca[7] = v3.z; sa[7] = v3.w;

        int b6 = lane & 1;
        int b7 = (lane >> 1) & 1;
        bool c7 = b7 != 0;
        int lbase = lane & ~3;
        int s0 = lbase | b6 | ((b7 ^ b6) << 1);
        int s1 = s0 ^ 1;

        // Initial product state (packed over qubit5)
        u64 amp2[32];
        {
            float w67 = (b6 ? sa[6] : ca[6]) * (b7 ? sa[7] : ca[7]);
            amp2[0] = pk2(w67 * ca[5], w67 * sa[5]);
            #pragma unroll
            for (int q = 0; q < 5; q++) {
                u64 cab = pk2(ca[q], ca[q]);
                u64 sab = pk2(sa[q], sa[q]);
                const int cnt = 1 << q;
                #pragma unroll
                for (int r = 0; r < 16; r++) {
                    if (r < cnt) {
                        amp2[r + cnt] = mul2(amp2[r], sab);
                        amp2[r]       = mul2(amp2[r], cab);
                    }
                }
            }
        }

        // tan-form constants (cheap; rebuilt per tile from smem)
        float tq[8];
        #pragma unroll
        for (int q = 0; q < 8; q++) tq[q] = sst[q] / sct[q];
        u64 nt0b = pk2(-tq[0], -tq[0]), pt0b = pk2(tq[0], tq[0]);
        u64 ntb[5], ptb[5];
        #pragma unroll
        for (int q = 1; q < 5; q++) {
            ntb[q] = pk2(-tq[q], -tq[q]);
            ptb[q] = pk2(tq[q], tq[q]);
        }
        u64 t5v = pk2(-tq[5], tq[5]);
        float sg6t = b6 ? tq[6] : -tq[6];
        float sg7t = b7 ? tq[7] : -tq[7];
        u64 sg6tb = pk2(sg6t, sg6t);
        u64 sg7tb = pk2(sg7t, sg7t);

        #pragma unroll
        for (int d = 0; d < 2; d++) {
            // CNOT(0,1)..(3,4): register renames (free)
            #pragma unroll
            for (int r = 0; r < 32; r++)
                if ((r & 1) && !(r & 2)) { u64 t = amp2[r]; amp2[r] = amp2[r | 2]; amp2[r | 2] = t; }
            #pragma unroll
            for (int r = 0; r < 32; r++)
                if ((r & 2) && !(r & 4)) { u64 t = amp2[r]; amp2[r] = amp2[r | 4]; amp2[r | 4] = t; }
            #pragma unroll
            for (int r = 0; r < 32; r++)
                if ((r & 4) && !(r & 8)) { u64 t = amp2[r]; amp2[r] = amp2[r | 8]; amp2[r | 8] = t; }
            #pragma unroll
            for (int r = 0; r < 32; r++)
                if ((r & 8) && !(r & 16)) { u64 t = amp2[r]; amp2[r] = amp2[r | 16]; amp2[r | 16] = t; }
            // CNOT(4,5) absorbed half-swap + merged CNOT(5,6)+(6,7) lane gather
            #pragma unroll
            for (int r = 0; r < 32; r++) {
                float lo, hi;
                up2(amp2[r], lo, hi);
                float x0 = (r & 16) ? hi : lo;
                float x1 = (r & 16) ? lo : hi;
                float nlo = __shfl_sync(FULLMASK, x0, s0);
                float nhi = __shfl_sync(FULLMASK, x1, s1);
                amp2[r] = pk2(nlo, nhi);
            }
            // fused CNOT(7,0)+RY(0), tan form
            #pragma unroll
            for (int r = 0; r < 32; r += 2) {
                u64 a0 = amp2[r], a1 = amp2[r + 1];
                u64 x0 = c7 ? a1 : a0;
                u64 x1 = c7 ? a0 : a1;
                amp2[r]     = fma2(nt0b, x1, x0);
                amp2[r + 1] = fma2(pt0b, x0, x1);
            }
            // RY(1..4), tan form
            #pragma unroll
            for (int q = 1; q < 5; q++) {
                const int bq = 1 << q;
                #pragma unroll
                for (int r = 0; r < 32; r++) {
                    if (!(r & bq)) {
                        int r2 = r | bq;
                        u64 a0 = amp2[r], a1 = amp2[r2];
                        amp2[r]  = fma2(ntb[q], a1, a0);
                        amp2[r2] = fma2(ptb[q], a0, a1);
                    }
                }
            }
            // RY(5): within-pair
            #pragma unroll
            for (int r = 0; r < 32; r++) {
                float lo, hi;
                up2(amp2[r], lo, hi);
                amp2[r] = fma2(t5v, pk2(hi, lo), amp2[r]);
            }
            // RY(6): lane xor1
            #pragma unroll
            for (int r = 0; r < 32; r++) {
                float lo, hi;
                up2(amp2[r], lo, hi);
                float plo = __shfl_xor_sync(FULLMASK, lo, 1);
                float phi = __shfl_xor_sync(FULLMASK, hi, 1);
                amp2[r] = fma2(sg6tb, pk2(plo, phi), amp2[r]);
            }
            // RY(7): lane xor2
            #pragma unroll
            for (int r = 0; r < 32; r++) {
                float lo, hi;
                up2(amp2[r], lo, hi);
                float plo = __shfl_xor_sync(FULLMASK, lo, 2);
                float phi = __shfl_xor_sync(FULLMASK, hi, 2);
                amp2[r] = fma2(sg7tb, pk2(plo, phi), amp2[r]);
            }
        }

        // Readout (g table carries F^2)
        int lsub = lane & 3;
        const u64* gp = (const u64*)(sG2 + lsub * 34);
        u64 tot2 = pk2(0.f, 0.f);
        #pragma unroll
        for (int r = 0; r < 32; r++) {
            u64 p2 = mul2(amp2[r], amp2[r]);
            tot2 = fma2(p2, gp[r], tot2);
        }
        float tlo, thi;
        up2(tot2, tlo, thi);
        float tot = tlo + thi;
        tot += __shfl_xor_sync(FULLMASK, tot, 1);
        tot += __shfl_xor_sync(FULLMASK, tot, 2);

        if (lsub == 0 && myrow < B)
            out[myrow] = tot + sbp;

        __syncthreads();   // scs reused next tile
    }
}

extern "C" void kernel_launch(void* const* d_in, const int* in_sizes, int n_in,
                              void* d_out, int out_size) {
    const float* E        = (const float*)d_in[0];
    const float* ln_gamma = (const float*)d_in[1];
    const float* ln_beta  = (const float*)d_in[2];
    const float* W_pre    = (const float*)d_in[3];
    const float* b_pre    = (const float*)d_in[4];
    const float* theta    = (const float*)d_in[5];
    const float* W_post   = (const float*)d_in[6];
    const float* b_post   = (const float*)d_in[7];
    float* out = (float*)d_out;
    int B = out_size;

    int numTiles = (B + 63) / 64;
    int sms = 148;
    cudaDeviceGetAttribute(&sms, cudaDevAttrMultiProcessorCount, 0);
    int grid = 2 * sms;
    if (grid > numTiles) grid = numTiles;

    qsco_fused<<<grid, 256>>>(E, W_pre, ln_gamma, ln_beta, b_pre,
                              theta, W_post, b_post, out, B, numTiles);
}

// round 16
// speedup vs baseline: 1.2095x; 1.0921x over previous
#include <cuda_runtime.h>
#include <cstdint>

#define FULLMASK 0xffffffffu
typedef unsigned long long u64;

// ---- f32x2 packed helpers (sm_103a) ----
__device__ __forceinline__ u64 pk2(float lo, float hi) {
    u64 r; asm("mov.b64 %0,{%1,%2};" : "=l"(r) : "f"(lo), "f"(hi)); return r;
}
__device__ __forceinline__ void up2(u64 v, float& lo, float& hi) {
    asm("mov.b64 {%0,%1},%2;" : "=f"(lo), "=f"(hi) : "l"(v));
}
__device__ __forceinline__ u64 fma2(u64 a, u64 b, u64 c) {
    u64 d; asm("fma.rn.f32x2 %0,%1,%2,%3;" : "=l"(d) : "l"(a), "l"(b), "l"(c)); return d;
}
__device__ __forceinline__ u64 mul2(u64 a, u64 b) {
    u64 d; asm("mul.rn.f32x2 %0,%1,%2;" : "=l"(d) : "l"(a), "l"(b)); return d;
}

// ============ Fused persistent kernel ============
// Block = 256 threads = 8 warps; tile = 64 rows; block loops over tiles.
// Phase 1: reduce-scatter reduction (each lane ends with sum/sumsq + its ONE dot).
// Phase 2: depth-1 CNOT ring folded into initial product construction (Ising-chain
//          doubling); depth-2 ring via verified gather path. tan-form RYs, F^2 in g.
__global__ __launch_bounds__(256, 2) void qsco_fused(const float* __restrict__ E,
                                                     const float* __restrict__ W_pre,
                                                     const float* __restrict__ ln_gamma,
                                                     const float* __restrict__ ln_beta,
                                                     const float* __restrict__ b_pre,
                                                     const float* __restrict__ theta,
                                                     const float* __restrict__ W_post,
                                                     const float* __restrict__ b_post,
                                                     float* __restrict__ out,
                                                     int B, int numTiles) {
    __shared__ float4 sWg4[8 * 128];            // 16 KB: gamma ⊙ W_pre
    __shared__ float sGw[32], sBw[32];
    __shared__ float sSg[8], sCq[8];
    __shared__ __align__(16) float2 scs[64 * 10];
    __shared__ __align__(16) float2 sG2[4 * 34];
    __shared__ float sct[8], sst[8], sbp;

    int tid = threadIdx.x;
    int lane = tid & 31;
    int wrp = tid >> 5;

    // ---- once-per-block prep ----
    {
        const float4* Wp4 = (const float4*)W_pre;
        const float4* g4  = (const float4*)ln_gamma;
        const float4* b4  = (const float4*)ln_beta;
        float gw[4], bw[4];
        #pragma unroll
        for (int j = 0; j < 4; j++) {
            int i = tid + 256 * j;
            float4 w = Wp4[i];
            float4 g = g4[i & 127];
            float4 b = b4[i & 127];
            float gsum = 0.f, bsum = 0.f;
            gsum = fmaf(g.x, w.x, gsum); gsum = fmaf(g.y, w.y, gsum);
            gsum = fmaf(g.z, w.z, gsum); gsum = fmaf(g.w, w.w, gsum);
            bsum = fmaf(b.x, w.x, bsum); bsum = fmaf(b.y, w.y, bsum);
            bsum = fmaf(b.z, w.z, bsum); bsum = fmaf(b.w, w.w, bsum);
            gw[j] = gsum; bw[j] = bsum;
            w.x *= g.x; w.y *= g.y; w.z *= g.z; w.w *= g.w;
            sWg4[i] = w;
        }
        #pragma unroll
        for (int m = 16; m; m >>= 1) {
            #pragma unroll
            for (int j = 0; j < 4; j++) {
                gw[j] += __shfl_xor_sync(FULLMASK, gw[j], m);
                bw[j] += __shfl_xor_sync(FULLMASK, bw[j], m);
            }
        }
        if (lane == 0) {
            #pragma unroll
            for (int j = 0; j < 4; j++) {
                sGw[wrp * 4 + j] = gw[j];
                sBw[wrp * 4 + j] = bw[j];
            }
        }
        if (tid < 8) {
            float h = 0.5f * theta[tid];
            sct[tid] = cosf(h);
            sst[tid] = sinf(h);
        }
        if (tid >= 128 && tid < 256) {
            int t = tid - 128;
            float fa = 1.f;
            #pragma unroll
            for (int i = 0; i < 8; i++) {
                float cc = cosf(0.5f * theta[i]);
                fa *= cc * cc;
            }
            float scale = fa * fa;
            int lsub = t >> 5, r = t & 31;
            int bb0 = r | (lsub << 6);
            int bb1 = bb0 | 32;
            float g0 = 0.f, g1 = 0.f;
            #pragma unroll
            for (int i = 0; i < 8; i++) {
                float w = W_post[i];
                g0 += w * (((bb0 >> i) & 1) ? -1.f : 1.f);
                g1 += w * (((bb1 >> i) & 1) ? -1.f : 1.f);
            }
            sG2[lsub * 34 + r] = make_float2(g0 * scale, g1 * scale);
        }
        if (tid == 16) sbp = b_post[0];
    }
    __syncthreads();
    if (tid < 8) {
        int h = tid & 1, jj = tid >> 1;
        float s = 0.f, cc = 0.f;
        #pragma unroll
        for (int m = 0; m < 4; m++) {
            s  += sGw[(4 * h + m) * 4 + jj];
            cc += sBw[(4 * h + m) * 4 + jj];
        }
        sSg[tid] = s;
        sCq[tid] = cc + b_pre[tid];
    }
    __syncthreads();

    // ---- persistent tile loop ----
    for (int tile = blockIdx.x; tile < numTiles; tile += gridDim.x) {
        int blkrow0 = tile * 64;

        // ---- Phase 1: angles, reduce-scatter reduction ----
        #pragma unroll
        for (int g = 0; g < 2; g++) {
            int row0 = blkrow0 + wrp * 8 + g * 4;

            float V[4][10];
            #pragma unroll
            for (int rr = 0; rr < 4; rr++)
                #pragma unroll
                for (int k = 0; k < 10; k++) V[rr][k] = 0.f;

            const float4* er[4];
            #pragma unroll
            for (int rr = 0; rr < 4; rr++) {
                int r = row0 + rr;
                if (r >= B) r = B - 1;
                er[rr] = (const float4*)(E + (size_t)r * 512);
            }

            #pragma unroll
            for (int j = 0; j < 4; j++) {
                float4 e[4];
                #pragma unroll
                for (int rr = 0; rr < 4; rr++) e[rr] = __ldcs(&er[rr][j * 32 + lane]);
                #pragma unroll
                for (int rr = 0; rr < 4; rr++) {
                    V[rr][0] += (e[rr].x + e[rr].y) + (e[rr].z + e[rr].w);
                    float ssv = V[rr][1];
                    ssv = fmaf(e[rr].x, e[rr].x, ssv);
                    ssv = fmaf(e[rr].y, e[rr].y, ssv);
                    ssv = fmaf(e[rr].z, e[rr].z, ssv);
                    ssv = fmaf(e[rr].w, e[rr].w, ssv);
                    V[rr][1] = ssv;
                }
                #pragma unroll
                for (int q = 0; q < 8; q++) {
                    float4 wv = sWg4[q * 128 + j * 32 + lane];
                    #pragma unroll
                    for (int rr = 0; rr < 4; rr++) {
                        float a = V[rr][2 + q];
                        a = fmaf(e[rr].x, wv.x, a);
                        a = fmaf(e[rr].y, wv.y, a);
                        a = fmaf(e[rr].z, wv.z, a);
                        a = fmaf(e[rr].w, wv.w, a);
                        V[rr][2 + q] = a;
                    }
                }
            }

            // Reduce-scatter: lane ends with its row's sum/sumsq + dot (lane&7)
            bool up  = (lane & 16) != 0;
            bool s8  = (lane & 8) != 0;
            bool s4  = (lane & 4) != 0;
            bool s2  = (lane & 2) != 0;
            bool s1b = (lane & 1) != 0;

            float A1v[10];
            #pragma unroll
            for (int k = 0; k < 10; k++) {
                float x = up ? V[0][k] : V[2][k];
                float p = __shfl_xor_sync(FULLMASK, x, 16);
                float keepA = (up ? V[2][k] : V[0][k]) + p;
                float y = up ? V[1][k] : V[3][k];
                float q = __shfl_xor_sync(FULLMASK, y, 16);
                float keepB = (up ? V[3][k] : V[1][k]) + q;
                float z = s8 ? keepA : keepB;
                float pz = __shfl_xor_sync(FULLMASK, z, 8);
                A1v[k] = (s8 ? keepB : keepA) + pz;
            }
            float s_sum = A1v[0], s_ss = A1v[1];
            s_sum += __shfl_xor_sync(FULLMASK, s_sum, 4);
            s_ss  += __shfl_xor_sync(FULLMASK, s_ss, 4);
            s_sum += __shfl_xor_sync(FULLMASK, s_sum, 2);
            s_ss  += __shfl_xor_sync(FULLMASK, s_ss, 2);
            s_sum += __shfl_xor_sync(FULLMASK, s_sum, 1);
            s_ss  += __shfl_xor_sync(FULLMASK, s_ss, 1);
            float D4[4];
            #pragma unroll
            for (int i = 0; i < 4; i++) {
                float x = s4 ? A1v[2 + i] : A1v[6 + i];
                float p = __shfl_xor_sync(FULLMASK, x, 4);
                D4[i] = (s4 ? A1v[6 + i] : A1v[2 + i]) + p;
            }
            float D2v[2];
            #pragma unroll
            for (int i = 0; i < 2; i++) {
                float x = s2 ? D4[i] : D4[2 + i];
                float p = __shfl_xor_sync(FULLMASK, x, 2);
                D2v[i] = (s2 ? D4[2 + i] : D4[i]) + p;
            }
            float dotM;
            {
                float x = s1b ? D2v[0] : D2v[1];
                float p = __shfl_xor_sync(FULLMASK, x, 1);
                dotM = (s1b ? D2v[1] : D2v[0]) + p;
            }

            const float inv512 = 1.0f / 512.0f;
            float mu = s_sum * inv512;
            float var = fmaf(-mu, mu, s_ss * inv512);
            float inv = rsqrtf(var + 1e-5f);

            int j = lane & 7;
            float ang = fmaf(inv, fmaf(-mu, sSg[j], dotM), sCq[j]);
            float s, c;
            __sincosf(0.5f * ang, &s, &c);
            int rowInBlk = wrp * 8 + g * 4 + (lane >> 3);
            scs[rowInBlk * 10 + j] = make_float2(c, s);
        }
        __syncthreads();

        // ---- Phase 2: circuit ----
        int rowInBlk = wrp * 8 + (lane >> 2);
        int myrow = blkrow0 + rowInBlk;

        const float4* ap = (const float4*)&scs[rowInBlk * 10];
        float4 v0 = ap[0], v1 = ap[1], v2 = ap[2], v3 = ap[3];
        float ca[8], sa[8];
        ca[0] = v0.x; sa[0] = v0.y; ca[1] = v0.z; sa[1] = v0.w;
        ca[2] = v1.x; sa[2] = v1.y; ca[3] = v1.z; sa[3] = v1.w;
        ca[4] = v2.x; sa[4] = v2.y; ca[5] = v2.z; sa[5] = v2.w;
        ca[6] = v3.x; sa[6] = v3.y; ca[7] = v3.z; sa[7] = v3.w;

        int b6 = lane & 1;
        int b7 = (lane >> 1) & 1;
        bool c7 = b7 != 0;
        int lbase = lane & ~3;
        int s0 = lbase | b6 | ((b7 ^ b6) << 1);
        int s1 = s0 ^ 1;

        // ---- Construction with depth-1 CNOT ring folded in ----
        // post-ring amp(b) = W0(b0)·W1(b0^b1)·W2(b1^b2)·W3(b2^b3)·W4(b3^b4)
        //                    ·W5(b4^b5)·W6(b5)·C7 with lane-flips by b6/b7.
        u64 amp2[32];
        {
            float f00 = b7 ? sa[0] : ca[0];
            float f01 = b7 ? ca[0] : sa[0];
            float f10 = b7 ? sa[1] : ca[1];
            float f11 = b7 ? ca[1] : sa[1];
            float C7c = (b6 ^ b7) ? sa[7] : ca[7];
            float f60 = b6 ? sa[6] : ca[6];
            float f61 = b6 ? ca[6] : sa[6];

            float t[32];
            float u0 = f00 * C7c, u1 = f01 * C7c;
            t[0] = u0 * f10; t[1] = u1 * f11; t[2] = u0 * f11; t[3] = u1 * f10;
            #pragma unroll
            for (int r = 0; r < 4; r++) {
                float wsame = ((r >> 1) & 1) ? sa[2] : ca[2];
                float wflip = ((r >> 1) & 1) ? ca[2] : sa[2];
                t[r + 4] = t[r] * wflip;
                t[r]     = t[r] * wsame;
            }
            #pragma unroll
            for (int r = 0; r < 8; r++) {
                float wsame = ((r >> 2) & 1) ? sa[3] : ca[3];
                float wflip = ((r >> 2) & 1) ? ca[3] : sa[3];
                t[r + 8] = t[r] * wflip;
                t[r]     = t[r] * wsame;
            }
            #pragma unroll
            for (int r = 0; r < 16; r++) {
                float wsame = ((r >> 3) & 1) ? sa[4] : ca[4];
                float wflip = ((r >> 3) & 1) ? ca[4] : sa[4];
                t[r + 16] = t[r] * wflip;
                t[r]      = t[r] * wsame;
            }
            float plo0 = ca[5] * f60, phi0 = sa[5] * f61;   // b4 = 0
            float plo1 = sa[5] * f60, phi1 = ca[5] * f61;   // b4 = 1
            #pragma unroll
            for (int r = 0; r < 32; r++) {
                float lo, hi;
                if ((r >> 4) & 1) { lo = t[r] * plo1; hi = t[r] * phi1; }
                else              { lo = t[r] * plo0; hi = t[r] * phi0; }
                amp2[r] = pk2(lo, hi);
            }
        }

        // tan-form constants
        float tq[8];
        #pragma unroll
        for (int q = 0; q < 8; q++) tq[q] = sst[q] / sct[q];
        u64 nt0b = pk2(-tq[0], -tq[0]), pt0b = pk2(tq[0], tq[0]);
        u64 ntb[5], ptb[5];
        #pragma unroll
        for (int q = 1; q < 5; q++) {
            ntb[q] = pk2(-tq[q], -tq[q]);
            ptb[q] = pk2(tq[q], tq[q]);
        }
        u64 t5v = pk2(-tq[5], tq[5]);
        float sg6t = b6 ? tq[6] : -tq[6];
        float sg7t = b7 ? tq[7] : -tq[7];
        u64 sg6tb = pk2(sg6t, sg6t);
        u64 sg7tb = pk2(sg7t, sg7t);

        // ---- depth-1 RY layer (ring already folded) ----
        #pragma unroll
        for (int r = 0; r < 32; r += 2) {   // plain RY(0)
            u64 a0 = amp2[r], a1 = amp2[r + 1];
            amp2[r]     = fma2(nt0b, a1, a0);
            amp2[r + 1] = fma2(pt0b, a0, a1);
        }
        #pragma unroll
        for (int q = 1; q < 5; q++) {
            const int bq = 1 << q;
            #pragma unroll
            for (int r = 0; r < 32; r++) {
                if (!(r & bq)) {
                    int r2 = r | bq;
                    u64 a0 = amp2[r], a1 = amp2[r2];
                    amp2[r]  = fma2(ntb[q], a1, a0);
                    amp2[r2] = fma2(ptb[q], a0, a1);
                }
            }
        }
        #pragma unroll
        for (int r = 0; r < 32; r++) {   // RY(5)
            float lo, hi;
            up2(amp2[r], lo, hi);
            amp2[r] = fma2(t5v, pk2(hi, lo), amp2[r]);
        }
        #pragma unroll
        for (int r = 0; r < 32; r++) {   // RY(6)
            float lo, hi;
            up2(amp2[r], lo, hi);
            float plo = __shfl_xor_sync(FULLMASK, lo, 1);
            float phi = __shfl_xor_sync(FULLMASK, hi, 1);
            amp2[r] = fma2(sg6tb, pk2(plo, phi), amp2[r]);
        }
        #pragma unroll
        for (int r = 0; r < 32; r++) {   // RY(7)
            float lo, hi;
            up2(amp2[r], lo, hi);
            float plo = __shfl_xor_sync(FULLMASK, lo, 2);
            float phi = __shfl_xor_sync(FULLMASK, hi, 2);
            amp2[r] = fma2(sg7tb, pk2(plo, phi), amp2[r]);
        }

        // ---- depth-2: full ring + RY layer (verified path) ----
        #pragma unroll
        for (int r = 0; r < 32; r++)
            if ((r & 1) && !(r & 2)) { u64 t = amp2[r]; amp2[r] = amp2[r | 2]; amp2[r | 2] = t; }
        #pragma unroll
        for (int r = 0; r < 32; r++)
            if ((r & 2) && !(r & 4)) { u64 t = amp2[r]; amp2[r] = amp2[r | 4]; amp2[r | 4] = t; }
        #pragma unroll
        for (int r = 0; r < 32; r++)
            if ((r & 4) && !(r & 8)) { u64 t = amp2[r]; amp2[r] = amp2[r | 8]; amp2[r | 8] = t; }
        #pragma unroll
        for (int r = 0; r < 32; r++)
            if ((r & 8) && !(r & 16)) { u64 t = amp2[r]; amp2[r] = amp2[r | 16]; amp2[r | 16] = t; }
        #pragma unroll
        for (int r = 0; r < 32; r++) {
            float lo, hi;
            up2(amp2[r], lo, hi);
            float x0 = (r & 16) ? hi : lo;
            float x1 = (r & 16) ? lo : hi;
            float nlo = __shfl_sync(FULLMASK, x0, s0);
            float nhi = __shfl_sync(FULLMASK, x1, s1);
            amp2[r] = pk2(nlo, nhi);
        }
        #pragma unroll
        for (int r = 0; r < 32; r += 2) {   // fused CNOT(7,0)+RY(0)
            u64 a0 = amp2[r], a1 = amp2[r + 1];
            u64 x0 = c7 ? a1 : a0;
            u64 x1 = c7 ? a0 : a1;
            amp2[r]     = fma2(nt0b, x1, x0);
            amp2[r + 1] = fma2(pt0b, x0, x1);
        }
        #pragma unroll
        for (int q = 1; q < 5; q++) {
            const int bq = 1 << q;
            #pragma unroll
            for (int r = 0; r < 32; r++) {
                if (!(r & bq)) {
                    int r2 = r | bq;
                    u64 a0 = amp2[r], a1 = amp2[r2];
                    amp2[r]  = fma2(ntb[q], a1, a0);
                    amp2[r2] = fma2(ptb[q], a0, a1);
                }
            }
        }
        #pragma unroll
        for (int r = 0; r < 32; r++) {   // RY(5)
            float lo, hi;
            up2(amp2[r], lo, hi);
            amp2[r] = fma2(t5v, pk2(hi, lo), amp2[r]);
        }
        #pragma unroll
        for (int r = 0; r < 32; r++) {   // RY(6)
            float lo, hi;
            up2(amp2[r], lo, hi);
            float plo = __shfl_xor_sync(FULLMASK, lo, 1);
            float phi = __shfl_xor_sync(FULLMASK, hi, 1);
            amp2[r] = fma2(sg6tb, pk2(plo, phi), amp2[r]);
        }
        #pragma unroll
        for (int r = 0; r < 32; r++) {   // RY(7)
            float lo, hi;
            up2(amp2[r], lo, hi);
            float plo = __shfl_xor_sync(FULLMASK, lo, 2);
            float phi = __shfl_xor_sync(FULLMASK, hi, 2);
            amp2[r] = fma2(sg7tb, pk2(plo, phi), amp2[r]);
        }

        // ---- Readout (g table carries F^2) ----
        int lsub = lane & 3;
        const u64* gp = (const u64*)(sG2 + lsub * 34);
        u64 tot2 = pk2(0.f, 0.f);
        #pragma unroll
        for (int r = 0; r < 32; r++) {
            u64 p2 = mul2(amp2[r], amp2[r]);
            tot2 = fma2(p2, gp[r], tot2);
        }
        float tlo, thi;
        up2(tot2, tlo, thi);
        float tot = tlo + thi;
        tot += __shfl_xor_sync(FULLMASK, tot, 1);
        tot += __shfl_xor_sync(FULLMASK, tot, 2);

        if (lsub == 0 && myrow < B)
            out[myrow] = tot + sbp;

        __syncthreads();   // scs reused next tile
    }
}

extern "C" void kernel_launch(void* const* d_in, const int* in_sizes, int n_in,
                              void* d_out, int out_size) {
    const float* E        = (const float*)d_in[0];
    const float* ln_gamma = (const float*)d_in[1];
    const float* ln_beta  = (const float*)d_in[2];
    const float* W_pre    = (const float*)d_in[3];
    const float* b_pre    = (const float*)d_in[4];
    const float* theta    = (const float*)d_in[5];
    const float* W_post   = (const float*)d_in[6];
    const float* b_post   = (const float*)d_in[7];
    float* out = (float*)d_out;
    int B = out_size;

    int numTiles = (B + 63) / 64;
    int sms = 148;
    cudaDeviceGetAttribute(&sms, cudaDevAttrMultiProcessorCount, 0);
    int grid = 2 * sms;
    if (grid > numTiles) grid = numTiles;

    qsco_fused<<<grid, 256>>>(E, W_pre, ln_gamma, ln_beta, b_pre,
                              theta, W_post, b_post, out, B, numTiles);
}